// round 2
// baseline (speedup 1.0000x reference)
#include <cuda_runtime.h>
#include <cstdint>

#define BB 2
#define DD 64
#define MAXN 50000
#define MAXE 800000

// ---------------- static device scratch (no allocations allowed) -----------
__device__ float g_P[(size_t)BB * MAXN * DD];      // prev @ W^T
__device__ int   g_deg[MAXN];
__device__ int   g_off[MAXN + 1];
__device__ int   g_cur[MAXN];
__device__ uint2 g_adj[2 * MAXE];                  // (nbr, gate-bits)

// ---------------- small asm helpers ----------------------------------------
__device__ __forceinline__ unsigned long long pack2(float lo, float hi) {
    unsigned long long r;
    asm("mov.b64 %0, {%1, %2};" : "=l"(r) : "f"(lo), "f"(hi));
    return r;
}
__device__ __forceinline__ float2 unpack2(unsigned long long v) {
    float2 r;
    asm("mov.b64 {%0, %1}, %2;" : "=f"(r.x), "=f"(r.y) : "l"(v));
    return r;
}
__device__ __forceinline__ void ffma2(unsigned long long& d,
                                      unsigned long long a,
                                      unsigned long long b) {
    asm("fma.rn.f32x2 %0, %1, %2, %0;" : "+l"(d) : "l"(a), "l"(b));
}

// ---------------------------------------------------------------------------
// Transform: P = prev @ W^T.  GEMM M x 64 x 64, 64-row tiles, 256 threads,
// 4x4 micro-tile per thread, row-pairs packed into f32x2 FMAs.
// ---------------------------------------------------------------------------
__global__ __launch_bounds__(256)
void k_transform(const float* __restrict__ prev, const float* __restrict__ W,
                 int nRows)
{
    __shared__ float As[64][66];   // As[k][row], padded
    __shared__ float Wt[64][64];   // Wt[k][e]

    int tid = threadIdx.x;
    int row0 = blockIdx.x * 64;

    // stage W transposed (one-time, conflicts irrelevant)
#pragma unroll
    for (int j = 0; j < 4; j++) {
        int f4 = tid + j * 256;                 // 1024 float4 of W
        int e = f4 >> 4, k4 = f4 & 15;
        float4 w = reinterpret_cast<const float4*>(W)[f4];
        Wt[k4 * 4 + 0][e] = w.x;
        Wt[k4 * 4 + 1][e] = w.y;
        Wt[k4 * 4 + 2][e] = w.z;
        Wt[k4 * 4 + 3][e] = w.w;
    }
    // stage A tile transposed
#pragma unroll
    for (int j = 0; j < 4; j++) {
        int f4 = tid + j * 256;                 // 1024 float4 of tile
        int r = f4 >> 4, c4 = f4 & 15;
        float4 a = make_float4(0.f, 0.f, 0.f, 0.f);
        if (row0 + r < nRows)
            a = reinterpret_cast<const float4*>(prev)[(size_t)(row0 + r) * 16 + c4];
        As[c4 * 4 + 0][r] = a.x;
        As[c4 * 4 + 1][r] = a.y;
        As[c4 * 4 + 2][r] = a.z;
        As[c4 * 4 + 3][r] = a.w;
    }
    __syncthreads();

    int colg = tid & 15;          // output column group (4 cols)
    int rowg = tid >> 4;          // row group (4 rows)

    unsigned long long acc[2][4] = {};   // [rowpair][col], bits 0 == (0.f,0.f)

#pragma unroll 8
    for (int k = 0; k < 64; k++) {
        const unsigned long long* ar =
            reinterpret_cast<const unsigned long long*>(&As[k][rowg * 4]);
        unsigned long long A0 = ar[0];   // rows (4r, 4r+1)
        unsigned long long A1 = ar[1];   // rows (4r+2, 4r+3)
        float4 w = *reinterpret_cast<const float4*>(&Wt[k][colg * 4]);
        unsigned long long w0 = pack2(w.x, w.x);
        unsigned long long w1 = pack2(w.y, w.y);
        unsigned long long w2 = pack2(w.z, w.z);
        unsigned long long w3 = pack2(w.w, w.w);
        ffma2(acc[0][0], A0, w0); ffma2(acc[0][1], A0, w1);
        ffma2(acc[0][2], A0, w2); ffma2(acc[0][3], A0, w3);
        ffma2(acc[1][0], A1, w0); ffma2(acc[1][1], A1, w1);
        ffma2(acc[1][2], A1, w2); ffma2(acc[1][3], A1, w3);
    }

    float4* P4 = reinterpret_cast<float4*>(g_P);
#pragma unroll
    for (int p = 0; p < 2; p++) {
        float2 v0 = unpack2(acc[p][0]);
        float2 v1 = unpack2(acc[p][1]);
        float2 v2 = unpack2(acc[p][2]);
        float2 v3 = unpack2(acc[p][3]);
        int rA = row0 + rowg * 4 + p * 2;
        int rB = rA + 1;
        if (rA < nRows)
            P4[(size_t)rA * 16 + colg] = make_float4(v0.x, v1.x, v2.x, v3.x);
        if (rB < nRows)
            P4[(size_t)rB * 16 + colg] = make_float4(v0.y, v1.y, v2.y, v3.y);
    }
}

// ---------------------------------------------------------------------------
// CSR build
// ---------------------------------------------------------------------------
__global__ __launch_bounds__(256)
void k_zero(int N)
{
    int i = blockIdx.x * blockDim.x + threadIdx.x;
    if (i < N) g_deg[i] = 0;
}

__global__ __launch_bounds__(256)
void k_count(const int* __restrict__ edges, int E)
{
    int e = blockIdx.x * blockDim.x + threadIdx.x;
    if (e >= E) return;
    int u = edges[2 * (size_t)e];
    int v = edges[2 * (size_t)e + 1];
    atomicAdd(&g_deg[u], 1);      // no return use -> RED
    atomicAdd(&g_deg[v], 1);
}

__global__ __launch_bounds__(1024)
void k_scan(int N)
{
    __shared__ int sums[1024];
    int t = threadIdx.x;
    int chunk = (N + 1023) >> 10;
    int start = t * chunk;
    int end = start + chunk; if (end > N) end = N;

    int s = 0;
    for (int i = start; i < end; i++) s += g_deg[i];
    sums[t] = s;
    __syncthreads();

    // inclusive Hillis-Steele scan
    for (int d = 1; d < 1024; d <<= 1) {
        int o = (t >= d) ? sums[t - d] : 0;
        __syncthreads();
        sums[t] += o;
        __syncthreads();
    }

    int running = sums[t] - s;    // exclusive base
    for (int i = start; i < end; i++) {
        g_off[i] = running;
        g_cur[i] = running;
        running += g_deg[i];
    }
    if (t == 1023) g_off[N] = sums[1023];
}

__global__ __launch_bounds__(256)
void k_fill(const int* __restrict__ edges, const float* __restrict__ status,
            int E)
{
    int e = blockIdx.x * blockDim.x + threadIdx.x;
    if (e >= E) return;
    int u = edges[2 * (size_t)e];
    int v = edges[2 * (size_t)e + 1];
    unsigned int gb = __float_as_uint(status[e]);
    int p1 = atomicAdd(&g_cur[u], 1);
    g_adj[p1] = make_uint2((unsigned)v, gb);   // node u accumulates P[v]*g
    int p2 = atomicAdd(&g_cur[v], 1);
    g_adj[p2] = make_uint2((unsigned)u, gb);   // node v accumulates P[u]*g
}

// ---------------------------------------------------------------------------
// Gather + epilogue: one warp per node.
//   lanes: b = lane>>4 (batch), c = lane&15 (float4 chunk of the 64-float row)
//   acc = sum over neighbors (m,g): P[b][m] * g
//   out[b][n] = leaky_relu(node + edge + acc)
// ---------------------------------------------------------------------------
__global__ __launch_bounds__(256)
void k_gather_final(const float* __restrict__ nodef,
                    const float* __restrict__ edgef,
                    float* __restrict__ out, int N)
{
    int warp = (blockIdx.x * blockDim.x + threadIdx.x) >> 5;
    if (warp >= N) return;
    int lane = threadIdx.x & 31;
    int b = lane >> 4;
    int c = lane & 15;

    int beg = g_off[warp];
    int end = g_off[warp + 1];

    const float4* P4 = reinterpret_cast<const float4*>(g_P);
    size_t bbase = (size_t)b * N;

    float4 acc0 = make_float4(0.f, 0.f, 0.f, 0.f);
    float4 acc1 = make_float4(0.f, 0.f, 0.f, 0.f);

    int e = beg;
    for (; e + 1 < end; e += 2) {
        uint2 a0 = g_adj[e];
        uint2 a1 = g_adj[e + 1];
        float g0 = __uint_as_float(a0.y);
        float g1 = __uint_as_float(a1.y);
        float4 p0 = __ldg(P4 + (bbase + a0.x) * 16 + c);
        float4 p1 = __ldg(P4 + (bbase + a1.x) * 16 + c);
        acc0.x += p0.x * g0; acc0.y += p0.y * g0;
        acc0.z += p0.z * g0; acc0.w += p0.w * g0;
        acc1.x += p1.x * g1; acc1.y += p1.y * g1;
        acc1.z += p1.z * g1; acc1.w += p1.w * g1;
    }
    if (e < end) {
        uint2 a0 = g_adj[e];
        float g0 = __uint_as_float(a0.y);
        float4 p0 = __ldg(P4 + (bbase + a0.x) * 16 + c);
        acc0.x += p0.x * g0; acc0.y += p0.y * g0;
        acc0.z += p0.z * g0; acc0.w += p0.w * g0;
    }

    size_t o = (bbase + warp) * 16 + c;
    float4 nf = reinterpret_cast<const float4*>(nodef)[o];
    float4 ef = reinterpret_cast<const float4*>(edgef)[o];

    float4 s;
    s.x = nf.x + ef.x + acc0.x + acc1.x;
    s.y = nf.y + ef.y + acc0.y + acc1.y;
    s.z = nf.z + ef.z + acc0.z + acc1.z;
    s.w = nf.w + ef.w + acc0.w + acc1.w;
    s.x = (s.x >= 0.f) ? s.x : 0.01f * s.x;
    s.y = (s.y >= 0.f) ? s.y : 0.01f * s.y;
    s.z = (s.z >= 0.f) ? s.z : 0.01f * s.z;
    s.w = (s.w >= 0.f) ? s.w : 0.01f * s.w;

    reinterpret_cast<float4*>(out)[o] = s;
}

// ---------------------------------------------------------------------------
extern "C" void kernel_launch(void* const* d_in, const int* in_sizes, int n_in,
                              void* d_out, int out_size)
{
    const float* prev  = (const float*)d_in[0];
    const int*   edges = (const int*)  d_in[1];
    const float* nodef = (const float*)d_in[2];
    const float* edgef = (const float*)d_in[3];
    const float* stat  = (const float*)d_in[4];
    const float* W     = (const float*)d_in[5];
    float* out = (float*)d_out;

    int E     = in_sizes[4];
    int nRows = in_sizes[0] / DD;   // B*N
    int N     = nRows / BB;

    // CSR build
    k_zero <<<(N + 255) / 256, 256>>>(N);
    k_count<<<(E + 255) / 256, 256>>>(edges, E);
    k_scan <<<1, 1024>>>(N);
    k_fill <<<(E + 255) / 256, 256>>>(edges, stat, E);

    // P = prev @ W^T
    k_transform<<<(nRows + 63) / 64, 256>>>(prev, W, nRows);

    // gather + epilogue (one warp per node)
    long long th = (long long)N * 32;
    k_gather_final<<<(unsigned)((th + 255) / 256), 256>>>(nodef, edgef, out, N);
}

// round 3
// speedup vs baseline: 1.2019x; 1.2019x over previous
#include <cuda_runtime.h>
#include <cstdint>

#define BB 2
#define DD 64
#define MAXN 50000
#define MAXE 800000

// ---------------- static device scratch (no allocations allowed) -----------
__device__ float g_P[(size_t)BB * MAXN * DD];      // prev @ W^T
__device__ int   g_deg[MAXN];
__device__ int   g_off[MAXN + 1];
__device__ uint2 g_rank[MAXE];                     // (rank_u, rank_v) per edge
__device__ uint2 g_adj[2 * MAXE];                  // (nbr, gate-bits)

// ---------------- small asm helpers ----------------------------------------
__device__ __forceinline__ unsigned long long pack2(float lo, float hi) {
    unsigned long long r;
    asm("mov.b64 %0, {%1, %2};" : "=l"(r) : "f"(lo), "f"(hi));
    return r;
}
__device__ __forceinline__ float2 unpack2(unsigned long long v) {
    float2 r;
    asm("mov.b64 {%0, %1}, %2;" : "=f"(r.x), "=f"(r.y) : "l"(v));
    return r;
}
__device__ __forceinline__ void ffma2(unsigned long long& d,
                                      unsigned long long a,
                                      unsigned long long b) {
    asm("fma.rn.f32x2 %0, %1, %2, %0;" : "+l"(d) : "l"(a), "l"(b));
}

// ---------------------------------------------------------------------------
// Transform: P = prev @ W^T.  64-row tiles, 256 threads, 4x4 micro-tile
// per thread with f32x2 packed FMAs.
// ---------------------------------------------------------------------------
__global__ __launch_bounds__(256)
void k_transform(const float* __restrict__ prev, const float* __restrict__ W,
                 int nRows)
{
    __shared__ float As[64][66];   // As[k][row], padded
    __shared__ float Wt[64][64];   // Wt[k][e]

    int tid = threadIdx.x;
    int row0 = blockIdx.x * 64;

#pragma unroll
    for (int j = 0; j < 4; j++) {
        int f4 = tid + j * 256;
        int e = f4 >> 4, k4 = f4 & 15;
        float4 w = reinterpret_cast<const float4*>(W)[f4];
        Wt[k4 * 4 + 0][e] = w.x;
        Wt[k4 * 4 + 1][e] = w.y;
        Wt[k4 * 4 + 2][e] = w.z;
        Wt[k4 * 4 + 3][e] = w.w;
    }
#pragma unroll
    for (int j = 0; j < 4; j++) {
        int f4 = tid + j * 256;
        int r = f4 >> 4, c4 = f4 & 15;
        float4 a = make_float4(0.f, 0.f, 0.f, 0.f);
        if (row0 + r < nRows)
            a = reinterpret_cast<const float4*>(prev)[(size_t)(row0 + r) * 16 + c4];
        As[c4 * 4 + 0][r] = a.x;
        As[c4 * 4 + 1][r] = a.y;
        As[c4 * 4 + 2][r] = a.z;
        As[c4 * 4 + 3][r] = a.w;
    }
    __syncthreads();

    int colg = tid & 15;
    int rowg = tid >> 4;

    unsigned long long acc[2][4] = {};

#pragma unroll 8
    for (int k = 0; k < 64; k++) {
        const unsigned long long* ar =
            reinterpret_cast<const unsigned long long*>(&As[k][rowg * 4]);
        unsigned long long A0 = ar[0];
        unsigned long long A1 = ar[1];
        float4 w = *reinterpret_cast<const float4*>(&Wt[k][colg * 4]);
        unsigned long long w0 = pack2(w.x, w.x);
        unsigned long long w1 = pack2(w.y, w.y);
        unsigned long long w2 = pack2(w.z, w.z);
        unsigned long long w3 = pack2(w.w, w.w);
        ffma2(acc[0][0], A0, w0); ffma2(acc[0][1], A0, w1);
        ffma2(acc[0][2], A0, w2); ffma2(acc[0][3], A0, w3);
        ffma2(acc[1][0], A1, w0); ffma2(acc[1][1], A1, w1);
        ffma2(acc[1][2], A1, w2); ffma2(acc[1][3], A1, w3);
    }

    float4* P4 = reinterpret_cast<float4*>(g_P);
#pragma unroll
    for (int p = 0; p < 2; p++) {
        float2 v0 = unpack2(acc[p][0]);
        float2 v1 = unpack2(acc[p][1]);
        float2 v2 = unpack2(acc[p][2]);
        float2 v3 = unpack2(acc[p][3]);
        int rA = row0 + rowg * 4 + p * 2;
        int rB = rA + 1;
        if (rA < nRows)
            P4[(size_t)rA * 16 + colg] = make_float4(v0.x, v1.x, v2.x, v3.x);
        if (rB < nRows)
            P4[(size_t)rB * 16 + colg] = make_float4(v0.y, v1.y, v2.y, v3.y);
    }
}

// ---------------------------------------------------------------------------
// CSR build
// ---------------------------------------------------------------------------
__global__ __launch_bounds__(256)
void k_zero(int N)
{
    int i = blockIdx.x * blockDim.x + threadIdx.x;
    if (i < N) g_deg[i] = 0;
}

// Count degrees AND record each endpoint's rank within its node (the only
// atomic pass in the whole build).
__global__ __launch_bounds__(256)
void k_count_rank(const int* __restrict__ edges, int E)
{
    int e = blockIdx.x * blockDim.x + threadIdx.x;
    if (e >= E) return;
    int u = edges[2 * (size_t)e];
    int v = edges[2 * (size_t)e + 1];
    unsigned ru = atomicAdd(&g_deg[u], 1);   // independent -> both in flight
    unsigned rv = atomicAdd(&g_deg[v], 1);
    g_rank[e] = make_uint2(ru, rv);
}

__global__ __launch_bounds__(1024)
void k_scan(int N)
{
    __shared__ int sums[1024];
    int t = threadIdx.x;
    int chunk = (N + 1023) >> 10;
    int start = t * chunk;
    int end = start + chunk; if (end > N) end = N;

    int s = 0;
    for (int i = start; i < end; i++) s += g_deg[i];
    sums[t] = s;
    __syncthreads();

    for (int d = 1; d < 1024; d <<= 1) {
        int o = (t >= d) ? sums[t - d] : 0;
        __syncthreads();
        sums[t] += o;
        __syncthreads();
    }

    int running = sums[t] - s;
    for (int i = start; i < end; i++) {
        g_off[i] = running;
        running += g_deg[i];
    }
    if (t == 1023) g_off[N] = sums[1023];
}

// Atomic-free fill: slot = off[node] + recorded rank. Full MLP.
__global__ __launch_bounds__(256)
void k_fill(const int* __restrict__ edges, const float* __restrict__ status,
            int E)
{
    int e = blockIdx.x * blockDim.x + threadIdx.x;
    if (e >= E) return;
    int u = edges[2 * (size_t)e];
    int v = edges[2 * (size_t)e + 1];
    uint2 r = g_rank[e];
    unsigned gb = __float_as_uint(status[e]);
    int pu = g_off[u] + (int)r.x;
    int pv = g_off[v] + (int)r.y;
    g_adj[pu] = make_uint2((unsigned)v, gb);   // node u accumulates P[v]*g
    g_adj[pv] = make_uint2((unsigned)u, gb);   // node v accumulates P[u]*g
}

// ---------------------------------------------------------------------------
// Gather + epilogue: one warp per node, 4-deep unrolled neighbor loop.
//   lanes: b = lane>>4 (batch), c = lane&15 (float4 chunk)
// ---------------------------------------------------------------------------
__global__ __launch_bounds__(256)
void k_gather_final(const float* __restrict__ nodef,
                    const float* __restrict__ edgef,
                    float* __restrict__ out, int N)
{
    int warp = (blockIdx.x * blockDim.x + threadIdx.x) >> 5;
    if (warp >= N) return;
    int lane = threadIdx.x & 31;
    int b = lane >> 4;
    int c = lane & 15;

    int beg = g_off[warp];
    int end = g_off[warp + 1];

    const float4* P4 = reinterpret_cast<const float4*>(g_P);
    size_t bbase = (size_t)b * N;

    float4 acc0 = make_float4(0.f, 0.f, 0.f, 0.f);
    float4 acc1 = make_float4(0.f, 0.f, 0.f, 0.f);
    float4 acc2 = make_float4(0.f, 0.f, 0.f, 0.f);
    float4 acc3 = make_float4(0.f, 0.f, 0.f, 0.f);

    int e = beg;
    for (; e + 3 < end; e += 4) {
        uint2 a0 = g_adj[e];
        uint2 a1 = g_adj[e + 1];
        uint2 a2 = g_adj[e + 2];
        uint2 a3 = g_adj[e + 3];
        float4 p0 = __ldg(P4 + (bbase + a0.x) * 16 + c);
        float4 p1 = __ldg(P4 + (bbase + a1.x) * 16 + c);
        float4 p2 = __ldg(P4 + (bbase + a2.x) * 16 + c);
        float4 p3 = __ldg(P4 + (bbase + a3.x) * 16 + c);
        float g0 = __uint_as_float(a0.y);
        float g1 = __uint_as_float(a1.y);
        float g2 = __uint_as_float(a2.y);
        float g3 = __uint_as_float(a3.y);
        acc0.x += p0.x * g0; acc0.y += p0.y * g0;
        acc0.z += p0.z * g0; acc0.w += p0.w * g0;
        acc1.x += p1.x * g1; acc1.y += p1.y * g1;
        acc1.z += p1.z * g1; acc1.w += p1.w * g1;
        acc2.x += p2.x * g2; acc2.y += p2.y * g2;
        acc2.z += p2.z * g2; acc2.w += p2.w * g2;
        acc3.x += p3.x * g3; acc3.y += p3.y * g3;
        acc3.z += p3.z * g3; acc3.w += p3.w * g3;
    }
    for (; e < end; e++) {
        uint2 a0 = g_adj[e];
        float g0 = __uint_as_float(a0.y);
        float4 p0 = __ldg(P4 + (bbase + a0.x) * 16 + c);
        acc0.x += p0.x * g0; acc0.y += p0.y * g0;
        acc0.z += p0.z * g0; acc0.w += p0.w * g0;
    }

    size_t o = (bbase + warp) * 16 + c;
    float4 nf = reinterpret_cast<const float4*>(nodef)[o];
    float4 ef = reinterpret_cast<const float4*>(edgef)[o];

    float4 s;
    s.x = nf.x + ef.x + (acc0.x + acc1.x) + (acc2.x + acc3.x);
    s.y = nf.y + ef.y + (acc0.y + acc1.y) + (acc2.y + acc3.y);
    s.z = nf.z + ef.z + (acc0.z + acc1.z) + (acc2.z + acc3.z);
    s.w = nf.w + ef.w + (acc0.w + acc1.w) + (acc2.w + acc3.w);
    s.x = (s.x >= 0.f) ? s.x : 0.01f * s.x;
    s.y = (s.y >= 0.f) ? s.y : 0.01f * s.y;
    s.z = (s.z >= 0.f) ? s.z : 0.01f * s.z;
    s.w = (s.w >= 0.f) ? s.w : 0.01f * s.w;

    reinterpret_cast<float4*>(out)[o] = s;
}

// ---------------------------------------------------------------------------
extern "C" void kernel_launch(void* const* d_in, const int* in_sizes, int n_in,
                              void* d_out, int out_size)
{
    const float* prev  = (const float*)d_in[0];
    const int*   edges = (const int*)  d_in[1];
    const float* nodef = (const float*)d_in[2];
    const float* edgef = (const float*)d_in[3];
    const float* stat  = (const float*)d_in[4];
    const float* W     = (const float*)d_in[5];
    float* out = (float*)d_out;

    int E     = in_sizes[4];
    int nRows = in_sizes[0] / DD;   // B*N
    int N     = nRows / BB;

    // CSR build (one atomic pass total)
    k_zero      <<<(N + 255) / 256, 256>>>(N);
    k_count_rank<<<(E + 255) / 256, 256>>>(edges, E);
    k_scan      <<<1, 1024>>>(N);
    k_fill      <<<(E + 255) / 256, 256>>>(edges, stat, E);

    // P = prev @ W^T (overlaps nothing but is independent of the CSR build
    // until the gather; scheduler can overlap it with build kernels only via
    // stream semantics — kept in-order for capture safety)
    k_transform<<<(nRows + 63) / 64, 256>>>(prev, W, nRows);

    // gather + epilogue (one warp per node)
    long long th = (long long)N * 32;
    k_gather_final<<<(unsigned)((th + 255) / 256), 256>>>(nodef, edgef, out, N);
}

// round 5
// speedup vs baseline: 1.2715x; 1.0580x over previous
#include <cuda_runtime.h>
#include <cuda_fp16.h>
#include <cstdint>

#define BB 2
#define DD 64
#define MAXN 50000
#define MAXE 800000

// ---------------- static device scratch (no allocations allowed) -----------
// P stored fp16, interleaved [node][batch][64] = 128 halves = 32 uint2 / node.
__device__ uint2 g_Ph[(size_t)MAXN * 32];
__device__ int   g_deg[MAXN];
__device__ int   g_off[MAXN + 1];
__device__ uint2 g_rank[MAXE];                 // (rank_u, rank_v) per edge
__device__ uint2 g_adj[2 * MAXE];              // (nbr, gate-bits)

// ---------------- small helpers ---------------------------------------------
__device__ __forceinline__ unsigned long long pack2(float lo, float hi) {
    unsigned long long r;
    asm("mov.b64 %0, {%1, %2};" : "=l"(r) : "f"(lo), "f"(hi));
    return r;
}
__device__ __forceinline__ float2 unpack2(unsigned long long v) {
    float2 r;
    asm("mov.b64 {%0, %1}, %2;" : "=f"(r.x), "=f"(r.y) : "l"(v));
    return r;
}
__device__ __forceinline__ void ffma2(unsigned long long& d,
                                      unsigned long long a,
                                      unsigned long long b) {
    asm("fma.rn.f32x2 %0, %1, %2, %0;" : "+l"(d) : "l"(a), "l"(b));
}
__device__ __forceinline__ unsigned pack_h2(float a, float b) {
    __half2 h = __floats2half2_rn(a, b);
    return *reinterpret_cast<unsigned*>(&h);
}
__device__ __forceinline__ float2 unpack_h2(unsigned u) {
    __half2 h = *reinterpret_cast<__half2*>(&u);
    return __half22float2(h);
}

// ---------------------------------------------------------------------------
// Transform: P = prev @ W^T (fp32 math), store fp16 interleaved.
// 64-row tiles, 256 threads, 4x4 micro-tile with f32x2 packed FMAs.
// ---------------------------------------------------------------------------
__global__ __launch_bounds__(256)
void k_transform(const float* __restrict__ prev, const float* __restrict__ W,
                 int nRows, int N)
{
    __shared__ float As[64][66];   // As[k][row]
    __shared__ float Wt[64][64];   // Wt[k][e]

    int tid = threadIdx.x;
    int row0 = blockIdx.x * 64;

#pragma unroll
    for (int j = 0; j < 4; j++) {
        int f4 = tid + j * 256;
        int e = f4 >> 4, k4 = f4 & 15;
        float4 w = reinterpret_cast<const float4*>(W)[f4];
        Wt[k4 * 4 + 0][e] = w.x;
        Wt[k4 * 4 + 1][e] = w.y;
        Wt[k4 * 4 + 2][e] = w.z;
        Wt[k4 * 4 + 3][e] = w.w;
    }
#pragma unroll
    for (int j = 0; j < 4; j++) {
        int f4 = tid + j * 256;
        int r = f4 >> 4, c4 = f4 & 15;
        float4 a = make_float4(0.f, 0.f, 0.f, 0.f);
        if (row0 + r < nRows)
            a = reinterpret_cast<const float4*>(prev)[(size_t)(row0 + r) * 16 + c4];
        As[c4 * 4 + 0][r] = a.x;
        As[c4 * 4 + 1][r] = a.y;
        As[c4 * 4 + 2][r] = a.z;
        As[c4 * 4 + 3][r] = a.w;
    }
    __syncthreads();

    int colg = tid & 15;
    int rowg = tid >> 4;

    unsigned long long acc[2][4] = {};

#pragma unroll 8
    for (int k = 0; k < 64; k++) {
        const unsigned long long* ar =
            reinterpret_cast<const unsigned long long*>(&As[k][rowg * 4]);
        unsigned long long A0 = ar[0];
        unsigned long long A1 = ar[1];
        float4 w = *reinterpret_cast<const float4*>(&Wt[k][colg * 4]);
        unsigned long long w0 = pack2(w.x, w.x);
        unsigned long long w1 = pack2(w.y, w.y);
        unsigned long long w2 = pack2(w.z, w.z);
        unsigned long long w3 = pack2(w.w, w.w);
        ffma2(acc[0][0], A0, w0); ffma2(acc[0][1], A0, w1);
        ffma2(acc[0][2], A0, w2); ffma2(acc[0][3], A0, w3);
        ffma2(acc[1][0], A1, w0); ffma2(acc[1][1], A1, w1);
        ffma2(acc[1][2], A1, w2); ffma2(acc[1][3], A1, w3);
    }

#pragma unroll
    for (int p = 0; p < 2; p++) {
        float2 v0 = unpack2(acc[p][0]);
        float2 v1 = unpack2(acc[p][1]);
        float2 v2 = unpack2(acc[p][2]);
        float2 v3 = unpack2(acc[p][3]);
        int rA = row0 + rowg * 4 + p * 2;
        int rB = rA + 1;
        if (rA < nRows) {
            int b = (rA >= N) ? 1 : 0;
            int n = rA - b * N;
            g_Ph[(size_t)n * 32 + b * 16 + colg] =
                make_uint2(pack_h2(v0.x, v1.x), pack_h2(v2.x, v3.x));
        }
        if (rB < nRows) {
            int b = (rB >= N) ? 1 : 0;
            int n = rB - b * N;
            g_Ph[(size_t)n * 32 + b * 16 + colg] =
                make_uint2(pack_h2(v0.y, v1.y), pack_h2(v2.y, v3.y));
        }
    }
}

// ---------------------------------------------------------------------------
// CSR build
// ---------------------------------------------------------------------------
__global__ __launch_bounds__(256)
void k_zero(int N)
{
    int i = blockIdx.x * blockDim.x + threadIdx.x;
    if (i < N) g_deg[i] = 0;
}

// 2 edges per thread: count degrees + record ranks (single atomic pass).
__global__ __launch_bounds__(256)
void k_count_rank(const int* __restrict__ edges, int E)
{
    int i = blockIdx.x * blockDim.x + threadIdx.x;
    int Eh = E >> 1;
    if (i < Eh) {
        int4 e2 = reinterpret_cast<const int4*>(edges)[i];
        unsigned r0 = atomicAdd(&g_deg[e2.x], 1);
        unsigned r1 = atomicAdd(&g_deg[e2.y], 1);
        unsigned r2 = atomicAdd(&g_deg[e2.z], 1);
        unsigned r3 = atomicAdd(&g_deg[e2.w], 1);
        reinterpret_cast<uint4*>(g_rank)[i] = make_uint4(r0, r1, r2, r3);
    } else if (i == Eh && (E & 1)) {
        int e = E - 1;
        int u = edges[2 * (size_t)e];
        int v = edges[2 * (size_t)e + 1];
        unsigned ru = atomicAdd(&g_deg[u], 1);
        unsigned rv = atomicAdd(&g_deg[v], 1);
        g_rank[e] = make_uint2(ru, rv);
    }
}

__global__ __launch_bounds__(1024)
void k_scan(int N)
{
    __shared__ int sums[1024];
    int t = threadIdx.x;
    int chunk = (N + 1023) >> 10;
    int start = t * chunk;
    int end = start + chunk; if (end > N) end = N;

    int s = 0;
    for (int i = start; i < end; i++) s += g_deg[i];
    sums[t] = s;
    __syncthreads();

    for (int d = 1; d < 1024; d <<= 1) {
        int o = (t >= d) ? sums[t - d] : 0;
        __syncthreads();
        sums[t] += o;
        __syncthreads();
    }

    int running = sums[t] - s;
    for (int i = start; i < end; i++) {
        g_off[i] = running;
        running += g_deg[i];
    }
    if (t == 1023) g_off[N] = sums[1023];
}

// Atomic-free fill, 2 edges per thread.
__global__ __launch_bounds__(256)
void k_fill(const int* __restrict__ edges, const float* __restrict__ status,
            int E)
{
    int i = blockIdx.x * blockDim.x + threadIdx.x;
    int Eh = E >> 1;
    if (i < Eh) {
        int4  e2 = reinterpret_cast<const int4*>(edges)[i];
        uint4 r2 = reinterpret_cast<const uint4*>(g_rank)[i];
        float2 st = reinterpret_cast<const float2*>(status)[i];
        unsigned g0 = __float_as_uint(st.x);
        unsigned g1 = __float_as_uint(st.y);
        int o0 = g_off[e2.x] + (int)r2.x;
        int o1 = g_off[e2.y] + (int)r2.y;
        int o2 = g_off[e2.z] + (int)r2.z;
        int o3 = g_off[e2.w] + (int)r2.w;
        g_adj[o0] = make_uint2((unsigned)e2.y, g0);
        g_adj[o1] = make_uint2((unsigned)e2.x, g0);
        g_adj[o2] = make_uint2((unsigned)e2.w, g1);
        g_adj[o3] = make_uint2((unsigned)e2.z, g1);
    } else if (i == Eh && (E & 1)) {
        int e = E - 1;
        int u = edges[2 * (size_t)e];
        int v = edges[2 * (size_t)e + 1];
        uint2 r = g_rank[e];
        unsigned gb = __float_as_uint(status[e]);
        g_adj[g_off[u] + (int)r.x] = make_uint2((unsigned)v, gb);
        g_adj[g_off[v] + (int)r.y] = make_uint2((unsigned)u, gb);
    }
}

// ---------------------------------------------------------------------------
// Gather + epilogue: one warp per node. Each lane owns 4 consecutive halves
// (uint2) of the interleaved 256B node record: lanes 0-15 batch0, 16-31 batch1.
// ---------------------------------------------------------------------------
__global__ __launch_bounds__(256)
void k_gather_final(const float* __restrict__ nodef,
                    const float* __restrict__ edgef,
                    float* __restrict__ out, int N)
{
    int node = (blockIdx.x * blockDim.x + threadIdx.x) >> 5;
    if (node >= N) return;
    int lane = threadIdx.x & 31;

    int beg = __ldg(&g_off[node]);
    int end = __ldg(&g_off[node + 1]);

    float4 acc0 = make_float4(0.f, 0.f, 0.f, 0.f);
    float4 acc1 = make_float4(0.f, 0.f, 0.f, 0.f);
    float4 acc2 = make_float4(0.f, 0.f, 0.f, 0.f);
    float4 acc3 = make_float4(0.f, 0.f, 0.f, 0.f);

    int e = beg;
    for (; e + 3 < end; e += 4) {
        uint2 a0 = g_adj[e];
        uint2 a1 = g_adj[e + 1];
        uint2 a2 = g_adj[e + 2];
        uint2 a3 = g_adj[e + 3];
        uint2 q0 = __ldg(g_Ph + (size_t)a0.x * 32 + lane);
        uint2 q1 = __ldg(g_Ph + (size_t)a1.x * 32 + lane);
        uint2 q2 = __ldg(g_Ph + (size_t)a2.x * 32 + lane);
        uint2 q3 = __ldg(g_Ph + (size_t)a3.x * 32 + lane);
        float g0 = __uint_as_float(a0.y);
        float g1 = __uint_as_float(a1.y);
        float g2 = __uint_as_float(a2.y);
        float g3 = __uint_as_float(a3.y);
        {
            float2 f01 = unpack_h2(q0.x), f23 = unpack_h2(q0.y);
            acc0.x += f01.x * g0; acc0.y += f01.y * g0;
            acc0.z += f23.x * g0; acc0.w += f23.y * g0;
        }
        {
            float2 f01 = unpack_h2(q1.x), f23 = unpack_h2(q1.y);
            acc1.x += f01.x * g1; acc1.y += f01.y * g1;
            acc1.z += f23.x * g1; acc1.w += f23.y * g1;
        }
        {
            float2 f01 = unpack_h2(q2.x), f23 = unpack_h2(q2.y);
            acc2.x += f01.x * g2; acc2.y += f01.y * g2;
            acc2.z += f23.x * g2; acc2.w += f23.y * g2;
        }
        {
            float2 f01 = unpack_h2(q3.x), f23 = unpack_h2(q3.y);
            acc3.x += f01.x * g3; acc3.y += f01.y * g3;
            acc3.z += f23.x * g3; acc3.w += f23.y * g3;
        }
    }
    for (; e < end; e++) {
        uint2 a0 = g_adj[e];
        float g0 = __uint_as_float(a0.y);
        uint2 q0 = __ldg(g_Ph + (size_t)a0.x * 32 + lane);
        float2 f01 = unpack_h2(q0.x), f23 = unpack_h2(q0.y);
        acc0.x += f01.x * g0; acc0.y += f01.y * g0;
        acc0.z += f23.x * g0; acc0.w += f23.y * g0;
    }

    int b = lane >> 4;
    int c = lane & 15;
    size_t o = ((size_t)b * N + node) * 16 + c;
    float4 nf = reinterpret_cast<const float4*>(nodef)[o];
    float4 ef = reinterpret_cast<const float4*>(edgef)[o];

    float4 s;
    s.x = nf.x + ef.x + (acc0.x + acc1.x) + (acc2.x + acc3.x);
    s.y = nf.y + ef.y + (acc0.y + acc1.y) + (acc2.y + acc3.y);
    s.z = nf.z + ef.z + (acc0.z + acc1.z) + (acc2.z + acc3.z);
    s.w = nf.w + ef.w + (acc0.w + acc1.w) + (acc2.w + acc3.w);
    s.x = (s.x >= 0.f) ? s.x : 0.01f * s.x;
    s.y = (s.y >= 0.f) ? s.y : 0.01f * s.y;
    s.z = (s.z >= 0.f) ? s.z : 0.01f * s.z;
    s.w = (s.w >= 0.f) ? s.w : 0.01f * s.w;

    reinterpret_cast<float4*>(out)[o] = s;
}

// ---------------------------------------------------------------------------
extern "C" void kernel_launch(void* const* d_in, const int* in_sizes, int n_in,
                              void* d_out, int out_size)
{
    const float* prev  = (const float*)d_in[0];
    const int*   edges = (const int*)  d_in[1];
    const float* nodef = (const float*)d_in[2];
    const float* edgef = (const float*)d_in[3];
    const float* stat  = (const float*)d_in[4];
    const float* W     = (const float*)d_in[5];
    float* out = (float*)d_out;

    int E     = in_sizes[4];
    int nRows = in_sizes[0] / DD;   // B*N
    int N     = nRows / BB;

    int Epair = (E >> 1) + 1;       // +1 slot handles odd-E tail thread

    k_zero      <<<(N + 255) / 256, 256>>>(N);
    k_count_rank<<<(Epair + 255) / 256, 256>>>(edges, E);
    k_scan      <<<1, 1024>>>(N);
    k_fill      <<<(Epair + 255) / 256, 256>>>(edges, stat, E);

    k_transform<<<(nRows + 63) / 64, 256>>>(prev, W, nRows, N);

    long long th = (long long)N * 32;
    k_gather_final<<<(unsigned)((th + 255) / 256), 256>>>(nodef, edgef, out, N);
}

// round 6
// speedup vs baseline: 1.6663x; 1.3104x over previous
#include <cuda_runtime.h>
#include <cuda_fp16.h>
#include <cstdint>

#define BB 2
#define DD 64
#define MAXN 50000
#define MAXE 800000
#define SCAN_B 1024

// ---------------- static device scratch (no allocations allowed) -----------
__device__ uint2 g_Ph[(size_t)MAXN * 32];      // fp16 P, [node][batch][64]
__device__ int   g_deg[MAXN];
__device__ int   g_off[MAXN + 1];
__device__ int   g_bsum[64];                   // block sums for scan
__device__ uint2 g_rank[MAXE];                 // (rank_u, rank_v) per edge
__device__ uint2 g_adj[2 * MAXE];              // (nbr, gate-bits)

// ---------------- small helpers ---------------------------------------------
__device__ __forceinline__ unsigned long long pack2(float lo, float hi) {
    unsigned long long r;
    asm("mov.b64 %0, {%1, %2};" : "=l"(r) : "f"(lo), "f"(hi));
    return r;
}
__device__ __forceinline__ float2 unpack2(unsigned long long v) {
    float2 r;
    asm("mov.b64 {%0, %1}, %2;" : "=f"(r.x), "=f"(r.y) : "l"(v));
    return r;
}
__device__ __forceinline__ void ffma2(unsigned long long& d,
                                      unsigned long long a,
                                      unsigned long long b) {
    asm("fma.rn.f32x2 %0, %1, %2, %0;" : "+l"(d) : "l"(a), "l"(b));
}
__device__ __forceinline__ unsigned pack_h2(float a, float b) {
    __half2 h = __floats2half2_rn(a, b);
    return *reinterpret_cast<unsigned*>(&h);
}
__device__ __forceinline__ float2 unpack_h2(unsigned u) {
    __half2 h = *reinterpret_cast<__half2*>(&u);
    return __half22float2(h);
}

// ---------------------------------------------------------------------------
// Transform: P = prev @ W^T (fp32 math), store fp16 interleaved.
// ---------------------------------------------------------------------------
__global__ __launch_bounds__(256)
void k_transform(const float* __restrict__ prev, const float* __restrict__ W,
                 int nRows, int N)
{
    __shared__ float As[64][66];
    __shared__ float Wt[64][64];

    int tid = threadIdx.x;
    int row0 = blockIdx.x * 64;

#pragma unroll
    for (int j = 0; j < 4; j++) {
        int f4 = tid + j * 256;
        int e = f4 >> 4, k4 = f4 & 15;
        float4 w = reinterpret_cast<const float4*>(W)[f4];
        Wt[k4 * 4 + 0][e] = w.x;
        Wt[k4 * 4 + 1][e] = w.y;
        Wt[k4 * 4 + 2][e] = w.z;
        Wt[k4 * 4 + 3][e] = w.w;
    }
#pragma unroll
    for (int j = 0; j < 4; j++) {
        int f4 = tid + j * 256;
        int r = f4 >> 4, c4 = f4 & 15;
        float4 a = make_float4(0.f, 0.f, 0.f, 0.f);
        if (row0 + r < nRows)
            a = reinterpret_cast<const float4*>(prev)[(size_t)(row0 + r) * 16 + c4];
        As[c4 * 4 + 0][r] = a.x;
        As[c4 * 4 + 1][r] = a.y;
        As[c4 * 4 + 2][r] = a.z;
        As[c4 * 4 + 3][r] = a.w;
    }
    __syncthreads();

    int colg = tid & 15;
    int rowg = tid >> 4;

    unsigned long long acc[2][4] = {};

#pragma unroll 8
    for (int k = 0; k < 64; k++) {
        const unsigned long long* ar =
            reinterpret_cast<const unsigned long long*>(&As[k][rowg * 4]);
        unsigned long long A0 = ar[0];
        unsigned long long A1 = ar[1];
        float4 w = *reinterpret_cast<const float4*>(&Wt[k][colg * 4]);
        unsigned long long w0 = pack2(w.x, w.x);
        unsigned long long w1 = pack2(w.y, w.y);
        unsigned long long w2 = pack2(w.z, w.z);
        unsigned long long w3 = pack2(w.w, w.w);
        ffma2(acc[0][0], A0, w0); ffma2(acc[0][1], A0, w1);
        ffma2(acc[0][2], A0, w2); ffma2(acc[0][3], A0, w3);
        ffma2(acc[1][0], A1, w0); ffma2(acc[1][1], A1, w1);
        ffma2(acc[1][2], A1, w2); ffma2(acc[1][3], A1, w3);
    }

#pragma unroll
    for (int p = 0; p < 2; p++) {
        float2 v0 = unpack2(acc[p][0]);
        float2 v1 = unpack2(acc[p][1]);
        float2 v2 = unpack2(acc[p][2]);
        float2 v3 = unpack2(acc[p][3]);
        int rA = row0 + rowg * 4 + p * 2;
        int rB = rA + 1;
        if (rA < nRows) {
            int b = (rA >= N) ? 1 : 0;
            int n = rA - b * N;
            g_Ph[(size_t)n * 32 + b * 16 + colg] =
                make_uint2(pack_h2(v0.x, v1.x), pack_h2(v2.x, v3.x));
        }
        if (rB < nRows) {
            int b = (rB >= N) ? 1 : 0;
            int n = rB - b * N;
            g_Ph[(size_t)n * 32 + b * 16 + colg] =
                make_uint2(pack_h2(v0.y, v1.y), pack_h2(v2.y, v3.y));
        }
    }
}

// ---------------------------------------------------------------------------
// CSR build: count+rank (single atomic pass), 3-phase parallel scan, fill.
// ---------------------------------------------------------------------------
__global__ __launch_bounds__(256)
void k_count_rank(const int* __restrict__ edges, int E)
{
    int i = blockIdx.x * blockDim.x + threadIdx.x;
    int Eh = E >> 1;
    if (i < Eh) {
        int4 e2 = reinterpret_cast<const int4*>(edges)[i];
        unsigned r0 = atomicAdd(&g_deg[e2.x], 1);
        unsigned r1 = atomicAdd(&g_deg[e2.y], 1);
        unsigned r2 = atomicAdd(&g_deg[e2.z], 1);
        unsigned r3 = atomicAdd(&g_deg[e2.w], 1);
        reinterpret_cast<uint4*>(g_rank)[i] = make_uint4(r0, r1, r2, r3);
    } else if (i == Eh && (E & 1)) {
        int e = E - 1;
        int u = edges[2 * (size_t)e];
        int v = edges[2 * (size_t)e + 1];
        unsigned ru = atomicAdd(&g_deg[u], 1);
        unsigned rv = atomicAdd(&g_deg[v], 1);
        g_rank[e] = make_uint2(ru, rv);
    }
}

// Phase A: per-block exclusive scan of g_deg into g_off; block total -> g_bsum.
__global__ __launch_bounds__(SCAN_B)
void k_scan_local(int N)
{
    __shared__ int sh[SCAN_B];
    int t = threadIdx.x;
    int i = blockIdx.x * SCAN_B + t;
    int d = (i < N) ? g_deg[i] : 0;
    sh[t] = d;
    __syncthreads();
    for (int s = 1; s < SCAN_B; s <<= 1) {
        int o = (t >= s) ? sh[t - s] : 0;
        __syncthreads();
        sh[t] += o;
        __syncthreads();
    }
    if (i < N) g_off[i] = sh[t] - d;          // exclusive local
    if (t == SCAN_B - 1) g_bsum[blockIdx.x] = sh[t];
}

// Phase B: scan block sums (<=64) and write grand total to g_off[N].
__global__ __launch_bounds__(64)
void k_scan_bsum(int nBlocks, int N)
{
    int t = threadIdx.x;
    int v = (t < nBlocks) ? g_bsum[t] : 0;
    // warp-level scan over 64 lanes via two warps + shared
    __shared__ int sh[64];
    sh[t] = v;
    __syncthreads();
    for (int s = 1; s < 64; s <<= 1) {
        int o = (t >= s) ? sh[t - s] : 0;
        __syncthreads();
        sh[t] += o;
        __syncthreads();
    }
    if (t < nBlocks) g_bsum[t] = sh[t] - v;   // exclusive base
    if (t == 63) g_off[N] = sh[63];
}

// Phase C: add block base.
__global__ __launch_bounds__(SCAN_B)
void k_scan_add(int N)
{
    int i = blockIdx.x * SCAN_B + threadIdx.x;
    if (i < N) g_off[i] += g_bsum[blockIdx.x];
}

// Atomic-free fill, 2 edges per thread.
__global__ __launch_bounds__(256)
void k_fill(const int* __restrict__ edges, const float* __restrict__ status,
            int E)
{
    int i = blockIdx.x * blockDim.x + threadIdx.x;
    int Eh = E >> 1;
    if (i < Eh) {
        int4  e2 = reinterpret_cast<const int4*>(edges)[i];
        uint4 r2 = reinterpret_cast<const uint4*>(g_rank)[i];
        float2 st = reinterpret_cast<const float2*>(status)[i];
        unsigned g0 = __float_as_uint(st.x);
        unsigned g1 = __float_as_uint(st.y);
        int o0 = g_off[e2.x] + (int)r2.x;
        int o1 = g_off[e2.y] + (int)r2.y;
        int o2 = g_off[e2.z] + (int)r2.z;
        int o3 = g_off[e2.w] + (int)r2.w;
        g_adj[o0] = make_uint2((unsigned)e2.y, g0);
        g_adj[o1] = make_uint2((unsigned)e2.x, g0);
        g_adj[o2] = make_uint2((unsigned)e2.w, g1);
        g_adj[o3] = make_uint2((unsigned)e2.z, g1);
    } else if (i == Eh && (E & 1)) {
        int e = E - 1;
        int u = edges[2 * (size_t)e];
        int v = edges[2 * (size_t)e + 1];
        uint2 r = g_rank[e];
        unsigned gb = __float_as_uint(status[e]);
        g_adj[g_off[u] + (int)r.x] = make_uint2((unsigned)v, gb);
        g_adj[g_off[v] + (int)r.y] = make_uint2((unsigned)u, gb);
    }
}

// ---------------------------------------------------------------------------
// Gather + epilogue: one warp per node, 8 loads in flight per iteration.
// ---------------------------------------------------------------------------
__global__ __launch_bounds__(256)
void k_gather_final(const float* __restrict__ nodef,
                    const float* __restrict__ edgef,
                    float* __restrict__ out, int N)
{
    int node = (blockIdx.x * blockDim.x + threadIdx.x) >> 5;
    if (node >= N) return;
    int lane = threadIdx.x & 31;

    int beg = __ldg(&g_off[node]);
    int end = __ldg(&g_off[node + 1]);

    float4 acc0 = make_float4(0.f, 0.f, 0.f, 0.f);
    float4 acc1 = make_float4(0.f, 0.f, 0.f, 0.f);
    float4 acc2 = make_float4(0.f, 0.f, 0.f, 0.f);
    float4 acc3 = make_float4(0.f, 0.f, 0.f, 0.f);

    int e = beg;
    for (; e + 7 < end; e += 8) {
        uint2 a0 = g_adj[e];
        uint2 a1 = g_adj[e + 1];
        uint2 a2 = g_adj[e + 2];
        uint2 a3 = g_adj[e + 3];
        uint2 a4 = g_adj[e + 4];
        uint2 a5 = g_adj[e + 5];
        uint2 a6 = g_adj[e + 6];
        uint2 a7 = g_adj[e + 7];
        uint2 q0 = __ldg(g_Ph + (size_t)a0.x * 32 + lane);
        uint2 q1 = __ldg(g_Ph + (size_t)a1.x * 32 + lane);
        uint2 q2 = __ldg(g_Ph + (size_t)a2.x * 32 + lane);
        uint2 q3 = __ldg(g_Ph + (size_t)a3.x * 32 + lane);
        uint2 q4 = __ldg(g_Ph + (size_t)a4.x * 32 + lane);
        uint2 q5 = __ldg(g_Ph + (size_t)a5.x * 32 + lane);
        uint2 q6 = __ldg(g_Ph + (size_t)a6.x * 32 + lane);
        uint2 q7 = __ldg(g_Ph + (size_t)a7.x * 32 + lane);
        float g0 = __uint_as_float(a0.y);
        float g1 = __uint_as_float(a1.y);
        float g2 = __uint_as_float(a2.y);
        float g3 = __uint_as_float(a3.y);
        float g4 = __uint_as_float(a4.y);
        float g5 = __uint_as_float(a5.y);
        float g6 = __uint_as_float(a6.y);
        float g7 = __uint_as_float(a7.y);
        {
            float2 f01 = unpack_h2(q0.x), f23 = unpack_h2(q0.y);
            acc0.x += f01.x * g0; acc0.y += f01.y * g0;
            acc0.z += f23.x * g0; acc0.w += f23.y * g0;
        }
        {
            float2 f01 = unpack_h2(q1.x), f23 = unpack_h2(q1.y);
            acc1.x += f01.x * g1; acc1.y += f01.y * g1;
            acc1.z += f23.x * g1; acc1.w += f23.y * g1;
        }
        {
            float2 f01 = unpack_h2(q2.x), f23 = unpack_h2(q2.y);
            acc2.x += f01.x * g2; acc2.y += f01.y * g2;
            acc2.z += f23.x * g2; acc2.w += f23.y * g2;
        }
        {
            float2 f01 = unpack_h2(q3.x), f23 = unpack_h2(q3.y);
            acc3.x += f01.x * g3; acc3.y += f01.y * g3;
            acc3.z += f23.x * g3; acc3.w += f23.y * g3;
        }
        {
            float2 f01 = unpack_h2(q4.x), f23 = unpack_h2(q4.y);
            acc0.x += f01.x * g4; acc0.y += f01.y * g4;
            acc0.z += f23.x * g4; acc0.w += f23.y * g4;
        }
        {
            float2 f01 = unpack_h2(q5.x), f23 = unpack_h2(q5.y);
            acc1.x += f01.x * g5; acc1.y += f01.y * g5;
            acc1.z += f23.x * g5; acc1.w += f23.y * g5;
        }
        {
            float2 f01 = unpack_h2(q6.x), f23 = unpack_h2(q6.y);
            acc2.x += f01.x * g6; acc2.y += f01.y * g6;
            acc2.z += f23.x * g6; acc2.w += f23.y * g6;
        }
        {
            float2 f01 = unpack_h2(q7.x), f23 = unpack_h2(q7.y);
            acc3.x += f01.x * g7; acc3.y += f01.y * g7;
            acc3.z += f23.x * g7; acc3.w += f23.y * g7;
        }
    }
    for (; e < end; e++) {
        uint2 a0 = g_adj[e];
        float g0 = __uint_as_float(a0.y);
        uint2 q0 = __ldg(g_Ph + (size_t)a0.x * 32 + lane);
        float2 f01 = unpack_h2(q0.x), f23 = unpack_h2(q0.y);
        acc0.x += f01.x * g0; acc0.y += f01.y * g0;
        acc0.z += f23.x * g0; acc0.w += f23.y * g0;
    }

    int b = lane >> 4;
    int c = lane & 15;
    size_t o = ((size_t)b * N + node) * 16 + c;
    float4 nf = reinterpret_cast<const float4*>(nodef)[o];
    float4 ef = reinterpret_cast<const float4*>(edgef)[o];

    float4 s;
    s.x = nf.x + ef.x + (acc0.x + acc1.x) + (acc2.x + acc3.x);
    s.y = nf.y + ef.y + (acc0.y + acc1.y) + (acc2.y + acc3.y);
    s.z = nf.z + ef.z + (acc0.z + acc1.z) + (acc2.z + acc3.z);
    s.w = nf.w + ef.w + (acc0.w + acc1.w) + (acc2.w + acc3.w);
    s.x = (s.x >= 0.f) ? s.x : 0.01f * s.x;
    s.y = (s.y >= 0.f) ? s.y : 0.01f * s.y;
    s.z = (s.z >= 0.f) ? s.z : 0.01f * s.z;
    s.w = (s.w >= 0.f) ? s.w : 0.01f * s.w;

    reinterpret_cast<float4*>(out)[o] = s;
}

// ---------------------------------------------------------------------------
extern "C" void kernel_launch(void* const* d_in, const int* in_sizes, int n_in,
                              void* d_out, int out_size)
{
    const float* prev  = (const float*)d_in[0];
    const int*   edges = (const int*)  d_in[1];
    const float* nodef = (const float*)d_in[2];
    const float* edgef = (const float*)d_in[3];
    const float* stat  = (const float*)d_in[4];
    const float* W     = (const float*)d_in[5];
    float* out = (float*)d_out;

    int E     = in_sizes[4];
    int nRows = in_sizes[0] / DD;   // B*N
    int N     = nRows / BB;

    int Epair   = (E >> 1) + 1;
    int nScanB  = (N + SCAN_B - 1) / SCAN_B;

    // zero degrees (capturable async memset on the device symbol)
    void* degPtr = nullptr;
    cudaGetSymbolAddress(&degPtr, g_deg);
    cudaMemsetAsync(degPtr, 0, (size_t)N * sizeof(int));

    k_count_rank<<<(Epair + 255) / 256, 256>>>(edges, E);
    k_scan_local<<<nScanB, SCAN_B>>>(N);
    k_scan_bsum <<<1, 64>>>(nScanB, N);
    k_scan_add  <<<nScanB, SCAN_B>>>(N);
    k_fill      <<<(Epair + 255) / 256, 256>>>(edges, stat, E);

    k_transform<<<(nRows + 63) / 64, 256>>>(prev, W, nRows, N);

    long long th = (long long)N * 32;
    k_gather_final<<<(unsigned)((th + 255) / 256), 256>>>(nodef, edgef, out, N);
}